// round 9
// baseline (speedup 1.0000x reference)
#include <cuda_runtime.h>
#include <cuda_fp16.h>
#include <cuda_bf16.h>
#include <cstdint>

#define N_PTS 100000
#define KNN   16
#define NK    (N_PTS * KNN)
#define EPSB  1e-5f

// ---------------- scratch (static device memory) -----------------------------
__device__ int    g_counts[N_PTS];
__device__ float  g_y1[(size_t)N_PTS * 64];    // pre-BN layer-1 output (fp32)
__device__ __half g_z[(size_t)N_PTS * 128];    // pre-BN layer-2 output (fp16)
__device__ float  g_stats1[2 * 64];            // weighted sum, sumsq
__device__ float  g_stats2[2 * 128];

// ---------------- helpers ------------------------------------------------------
__device__ __forceinline__ uint32_t smem_u32(const void* p) {
    uint32_t a;
    asm("{ .reg .u64 t; cvta.to.shared.u64 t, %1; cvt.u32.u64 %0, t; }"
        : "=r"(a) : "l"(p));
    return a;
}
__device__ __forceinline__ uint32_t swz(uint32_t off) {
    return off ^ ((off >> 3) & 0x70);   // 128B-row XOR swizzle, 16B granules
}
__device__ __forceinline__ void split_bf16(float v, __nv_bfloat16& hi,
                                           __nv_bfloat16& lo) {
    hi = __float2bfloat16(v);
    lo = __float2bfloat16(v - __bfloat162float(hi));
}
__device__ __forceinline__ void ldsm_x4(uint32_t* r, uint32_t addr) {
    asm volatile(
        "ldmatrix.sync.aligned.m8n8.x4.shared.b16 {%0,%1,%2,%3}, [%4];"
        : "=r"(r[0]), "=r"(r[1]), "=r"(r[2]), "=r"(r[3]) : "r"(addr));
}
__device__ __forceinline__ void ldsm_x2(uint32_t* r, uint32_t addr) {
    asm volatile(
        "ldmatrix.sync.aligned.m8n8.x2.shared.b16 {%0,%1}, [%2];"
        : "=r"(r[0]), "=r"(r[1]) : "r"(addr));
}
__device__ __forceinline__ void mma_bf16(float* c, const uint32_t* a,
                                         const uint32_t* b) {
    asm volatile(
        "mma.sync.aligned.m16n8k16.row.col.f32.bf16.bf16.f32 "
        "{%0,%1,%2,%3}, {%4,%5,%6,%7}, {%8,%9}, {%0,%1,%2,%3};"
        : "+f"(c[0]), "+f"(c[1]), "+f"(c[2]), "+f"(c[3])
        : "r"(a[0]), "r"(a[1]), "r"(a[2]), "r"(a[3]), "r"(b[0]), "r"(b[1]));
}
__device__ __forceinline__ float warp_sum8(float v) {
    // sum across the 8 lanes differing in bits 2..4 (same lane&3)
    v += __shfl_xor_sync(0xffffffffu, v, 4);
    v += __shfl_xor_sync(0xffffffffu, v, 8);
    v += __shfl_xor_sync(0xffffffffu, v, 16);
    return v;
}

// ---------------- small kernels ------------------------------------------------
__global__ void zero_kernel() {
    int i = blockIdx.x * blockDim.x + threadIdx.x;
    if (i < N_PTS) g_counts[i] = 0;
    if (i < 2 * 64) g_stats1[i] = 0.f;
    if (i < 2 * 128) g_stats2[i] = 0.f;
}

__global__ void count_kernel(const int4* __restrict__ idx4) {
    int i = blockIdx.x * blockDim.x + threadIdx.x;
    if (i < NK / 4) {
        int4 v = idx4[i];
        atomicAdd(&g_counts[v.x], 1);
        atomicAdd(&g_counts[v.y], 1);
        atomicAdd(&g_counts[v.z], 1);
        atomicAdd(&g_counts[v.w], 1);
    }
}

// ---------------- GEMM1 (HMMA): y1 = feat @ W1 + b1, weighted BN1 stats -------
// CTA: 128 rows x 64 cols, 8 warps as 4(row)x2(col); warp tile 32x32.
// bf16 hi/lo 3-term split, fp32 accumulate.
#define G1_AHI 0u            // 128 x 128B
#define G1_ALO 16384u
#define G1_BHI 32768u        // 64 x 128B  (Bt[n][k])
#define G1_BLO 40960u
#define G1_SMEM (49152 + 1024)

__global__ __launch_bounds__(256) void gemm1_mma(const float* __restrict__ feat,
                                                 const float* __restrict__ W1,
                                                 const float* __restrict__ b1) {
    extern __shared__ char dsm[];
    uint32_t raw = smem_u32(dsm);
    uint32_t sbase = (raw + 1023u) & ~1023u;
    char* smp = dsm + (sbase - raw);
    const int tid = threadIdx.x;
    const int wi = tid >> 5, lane = tid & 31;
    const int row0 = blockIdx.x * 128;

    // A plane: feat rows, bf16 hi/lo, swizzled 128B rows
    for (int f = tid; f < 4096; f += 256) {
        int r = f >> 5, c2 = (f & 31) * 2;
        float2 v = make_float2(0.f, 0.f);
        if (row0 + r < N_PTS) v = *(const float2*)&feat[(size_t)(row0 + r) * 64 + c2];
        __nv_bfloat16 hx, lx, hy, ly;
        split_bf16(v.x, hx, lx);
        split_bf16(v.y, hy, ly);
        uint32_t sw = swz((uint32_t)(r * 128 + c2 * 2));
        __nv_bfloat162 h2; h2.x = hx; h2.y = hy;
        __nv_bfloat162 l2; l2.x = lx; l2.y = ly;
        *(__nv_bfloat162*)(smp + G1_AHI + sw) = h2;
        *(__nv_bfloat162*)(smp + G1_ALO + sw) = l2;
    }
    // B plane: Bt[n][k] = W1[k][n]
    for (int f = tid; f < 4096; f += 256) {
        int k = f & 63, n = f >> 6;
        float v = W1[k * 64 + n];
        __nv_bfloat16 h, l;
        split_bf16(v, h, l);
        uint32_t sw = swz((uint32_t)(n * 128 + k * 2));
        *(__nv_bfloat16*)(smp + G1_BHI + sw) = h;
        *(__nv_bfloat16*)(smp + G1_BLO + sw) = l;
    }
    __syncthreads();

    const int mrow0 = (wi >> 1) * 32;   // warp row origin in tile
    const int ncol0 = (wi & 1) * 32;    // warp col origin

    float acc[2][4][4];
#pragma unroll
    for (int m = 0; m < 2; m++)
#pragma unroll
        for (int n = 0; n < 4; n++)
#pragma unroll
            for (int q = 0; q < 4; q++) acc[m][n][q] = 0.f;

#pragma unroll
    for (int ks = 0; ks < 4; ks++) {
        const uint32_t kb = (uint32_t)(ks * 32);   // k0*2 bytes
        uint32_t aH[2][4], aL[2][4], bH[4][2], bL[4][2];
        // A: rows mrow0 + m*16 + (lane&15); col halves via lane>>4
        uint32_t aoff = (uint32_t)((mrow0 + (lane & 15)) * 128) + kb + (uint32_t)((lane >> 4) * 16);
#pragma unroll
        for (int m = 0; m < 2; m++) {
            uint32_t sw = swz(aoff + (uint32_t)(m * 16 * 128));
            ldsm_x4(aH[m], sbase + G1_AHI + sw);
            ldsm_x4(aL[m], sbase + G1_ALO + sw);
        }
        // B: rows ncol0 + n*8 + (lane&7); k halves via (lane>>3)&1
        uint32_t boff = (uint32_t)((ncol0 + (lane & 7)) * 128) + kb + (uint32_t)(((lane >> 3) & 1) * 16);
#pragma unroll
        for (int n = 0; n < 4; n++) {
            uint32_t sw = swz(boff + (uint32_t)(n * 8 * 128));
            ldsm_x2(bH[n], sbase + G1_BHI + sw);
            ldsm_x2(bL[n], sbase + G1_BLO + sw);
        }
#pragma unroll
        for (int m = 0; m < 2; m++)
#pragma unroll
            for (int n = 0; n < 4; n++) {
                mma_bf16(acc[m][n], aH[m], bH[n]);
                mma_bf16(acc[m][n], aH[m], bL[n]);
                mma_bf16(acc[m][n], aL[m], bH[n]);
            }
    }

    // Epilogue: fragment layout c0:(g,t2) c1:(g,t2+1) c2:(g+8,t2) c3:(g+8,t2+1)
    const int g = lane >> 2, t = lane & 3;
    float ps[4][2], qs[4][2];
#pragma unroll
    for (int n = 0; n < 4; n++) { ps[n][0] = ps[n][1] = qs[n][0] = qs[n][1] = 0.f; }
#pragma unroll
    for (int m = 0; m < 2; m++) {
        int r0 = row0 + mrow0 + m * 16 + g;
        int r1 = r0 + 8;
        bool v0 = r0 < N_PTS, v1 = r1 < N_PTS;
        float w0 = v0 ? (float)g_counts[r0] : 0.f;
        float w1 = v1 ? (float)g_counts[r1] : 0.f;
#pragma unroll
        for (int n = 0; n < 4; n++) {
            int col = ncol0 + n * 8 + t * 2;
            float bc0 = b1[col], bc1 = b1[col + 1];
            float y00 = acc[m][n][0] + bc0, y01 = acc[m][n][1] + bc1;
            float y10 = acc[m][n][2] + bc0, y11 = acc[m][n][3] + bc1;
            if (v0) *(float2*)&g_y1[(size_t)r0 * 64 + col] = make_float2(y00, y01);
            if (v1) *(float2*)&g_y1[(size_t)r1 * 64 + col] = make_float2(y10, y11);
            ps[n][0] += w0 * y00 + w1 * y10;
            ps[n][1] += w0 * y01 + w1 * y11;
            qs[n][0] += w0 * y00 * y00 + w1 * y10 * y10;
            qs[n][1] += w0 * y01 * y01 + w1 * y11 * y11;
        }
    }
#pragma unroll
    for (int n = 0; n < 4; n++) {
        float s0 = warp_sum8(ps[n][0]);
        float s1 = warp_sum8(ps[n][1]);
        float q0 = warp_sum8(qs[n][0]);
        float q1 = warp_sum8(qs[n][1]);
        if (lane < 4) {
            int col = ncol0 + n * 8 + lane * 2;
            // each of lanes 0-3 owns its own column pair (t = lane)
            atomicAdd(&g_stats1[col], s0);
            atomicAdd(&g_stats1[col + 1], s1);
            atomicAdd(&g_stats1[64 + col], q0);
            atomicAdd(&g_stats1[64 + col + 1], q1);
        }
    }
}

// ---------------- GEMM2 (HMMA): h=relu(bn1(y1)); y2=h@W2+b2 -> fp16 + stats ---
// CTA: 64 rows x 128 cols, 8 warps as 2(row)x4(col); warp tile 32x32.
#define G2_AHI 0u            // 64 x 128B
#define G2_ALO 8192u
#define G2_BHI 16384u        // 128 x 128B
#define G2_BLO 32768u
#define G2_SB1 49152u        // scale[64] + bias[64]
#define G2_SMEM (49664 + 1024)

__global__ __launch_bounds__(256) void gemm2_mma(const float* __restrict__ W2,
                                                 const float* __restrict__ b2,
                                                 const float* __restrict__ gamma1,
                                                 const float* __restrict__ beta1) {
    extern __shared__ char dsm[];
    uint32_t raw = smem_u32(dsm);
    uint32_t sbase = (raw + 1023u) & ~1023u;
    char* smp = dsm + (sbase - raw);
    const int tid = threadIdx.x;
    const int wi = tid >> 5, lane = tid & 31;
    const int row0 = blockIdx.x * 64;

    if (tid < 64) {
        const float inv_m = 1.0f / (float)NK;
        float mean = g_stats1[tid] * inv_m;
        float var = g_stats1[64 + tid] * inv_m - mean * mean;
        float sc = gamma1[tid] * rsqrtf(var + EPSB);
        *(float*)(smp + G2_SB1 + tid * 4) = sc;
        *(float*)(smp + G2_SB1 + 256 + tid * 4) = beta1[tid] - mean * sc;
    }
    // B plane: Bt[n][k] = W2[k][n]
    for (int f = tid; f < 8192; f += 256) {
        int k = f & 63, n = f >> 6;
        float v = W2[k * 128 + n];
        __nv_bfloat16 h, l;
        split_bf16(v, h, l);
        uint32_t sw = swz((uint32_t)(n * 128 + k * 2));
        *(__nv_bfloat16*)(smp + G2_BHI + sw) = h;
        *(__nv_bfloat16*)(smp + G2_BLO + sw) = l;
    }
    __syncthreads();   // sb1 ready for A construction

    // A plane: h = relu(bn1(y1)), 64 rows x 64 k
    for (int f = tid; f < 2048; f += 256) {
        int r = f >> 5, c2 = (f & 31) * 2;
        float2 v = make_float2(0.f, 0.f);
        if (row0 + r < N_PTS) v = *(const float2*)&g_y1[(size_t)(row0 + r) * 64 + c2];
        float2 sc = *(const float2*)(smp + G2_SB1 + c2 * 4);
        float2 bi = *(const float2*)(smp + G2_SB1 + 256 + c2 * 4);
        float hx = fmaxf(fmaf(v.x, sc.x, bi.x), 0.f);
        float hy = fmaxf(fmaf(v.y, sc.y, bi.y), 0.f);
        __nv_bfloat16 hhx, llx, hhy, lly;
        split_bf16(hx, hhx, llx);
        split_bf16(hy, hhy, lly);
        uint32_t sw = swz((uint32_t)(r * 128 + c2 * 2));
        __nv_bfloat162 h2; h2.x = hhx; h2.y = hhy;
        __nv_bfloat162 l2; l2.x = llx; l2.y = lly;
        *(__nv_bfloat162*)(smp + G2_AHI + sw) = h2;
        *(__nv_bfloat162*)(smp + G2_ALO + sw) = l2;
    }
    __syncthreads();

    const int mrow0 = (wi >> 2) * 32;
    const int ncol0 = (wi & 3) * 32;

    float acc[2][4][4];
#pragma unroll
    for (int m = 0; m < 2; m++)
#pragma unroll
        for (int n = 0; n < 4; n++)
#pragma unroll
            for (int q = 0; q < 4; q++) acc[m][n][q] = 0.f;

#pragma unroll
    for (int ks = 0; ks < 4; ks++) {
        const uint32_t kb = (uint32_t)(ks * 32);
        uint32_t aH[2][4], aL[2][4], bH[4][2], bL[4][2];
        uint32_t aoff = (uint32_t)((mrow0 + (lane & 15)) * 128) + kb + (uint32_t)((lane >> 4) * 16);
#pragma unroll
        for (int m = 0; m < 2; m++) {
            uint32_t sw = swz(aoff + (uint32_t)(m * 16 * 128));
            ldsm_x4(aH[m], sbase + G2_AHI + sw);
            ldsm_x4(aL[m], sbase + G2_ALO + sw);
        }
        uint32_t boff = (uint32_t)((ncol0 + (lane & 7)) * 128) + kb + (uint32_t)(((lane >> 3) & 1) * 16);
#pragma unroll
        for (int n = 0; n < 4; n++) {
            uint32_t sw = swz(boff + (uint32_t)(n * 8 * 128));
            ldsm_x2(bH[n], sbase + G2_BHI + sw);
            ldsm_x2(bL[n], sbase + G2_BLO + sw);
        }
#pragma unroll
        for (int m = 0; m < 2; m++)
#pragma unroll
            for (int n = 0; n < 4; n++) {
                mma_bf16(acc[m][n], aH[m], bH[n]);
                mma_bf16(acc[m][n], aH[m], bL[n]);
                mma_bf16(acc[m][n], aL[m], bH[n]);
            }
    }

    const int g = lane >> 2, t = lane & 3;
    float ps[4][2], qs[4][2];
#pragma unroll
    for (int n = 0; n < 4; n++) { ps[n][0] = ps[n][1] = qs[n][0] = qs[n][1] = 0.f; }
#pragma unroll
    for (int m = 0; m < 2; m++) {
        int r0 = row0 + mrow0 + m * 16 + g;
        int r1 = r0 + 8;
        bool v0 = r0 < N_PTS, v1 = r1 < N_PTS;
        float w0 = v0 ? (float)g_counts[r0] : 0.f;
        float w1 = v1 ? (float)g_counts[r1] : 0.f;
#pragma unroll
        for (int n = 0; n < 4; n++) {
            int col = ncol0 + n * 8 + t * 2;
            float bc0 = b2[col], bc1 = b2[col + 1];
            float y00 = acc[m][n][0] + bc0, y01 = acc[m][n][1] + bc1;
            float y10 = acc[m][n][2] + bc0, y11 = acc[m][n][3] + bc1;
            if (v0) *(__half2*)&g_z[(size_t)r0 * 128 + col] = __floats2half2_rn(y00, y01);
            if (v1) *(__half2*)&g_z[(size_t)r1 * 128 + col] = __floats2half2_rn(y10, y11);
            ps[n][0] += w0 * y00 + w1 * y10;
            ps[n][1] += w0 * y01 + w1 * y11;
            qs[n][0] += w0 * y00 * y00 + w1 * y10 * y10;
            qs[n][1] += w0 * y01 * y01 + w1 * y11 * y11;
        }
    }
#pragma unroll
    for (int n = 0; n < 4; n++) {
        float s0 = warp_sum8(ps[n][0]);
        float s1 = warp_sum8(ps[n][1]);
        float q0 = warp_sum8(qs[n][0]);
        float q1 = warp_sum8(qs[n][1]);
        if (lane < 4) {
            int col = ncol0 + n * 8 + lane * 2;
            atomicAdd(&g_stats2[col], s0);
            atomicAdd(&g_stats2[col + 1], s1);
            atomicAdd(&g_stats2[128 + col], q0);
            atomicAdd(&g_stats2[128 + col + 1], q1);
        }
    }
}

// ---------------- gather + max/min pool + folded BN2 + ReLU -------------------
__global__ __launch_bounds__(256) void gather_max_kernel(
    const int* __restrict__ idx, const float* __restrict__ gamma2,
    const float* __restrict__ beta2, float* __restrict__ out) {
    int warp = (blockIdx.x * blockDim.x + threadIdx.x) >> 5;
    int lane = threadIdx.x & 31;
    int p = warp * 2 + (lane >> 4);
    if (p >= N_PTS) return;
    int half_lane = lane & 15;
    int c0 = half_lane * 8;

    int myidx = idx[p * 16 + half_lane];

    __half2 mx[4], mn[4];
#pragma unroll
    for (int j = 0; j < 4; j++) {
        mx[j] = __floats2half2_rn(-65504.f, -65504.f);
        mn[j] = __floats2half2_rn(65504.f, 65504.f);
    }

#pragma unroll
    for (int k = 0; k < 16; k++) {
        int r = __shfl_sync(0xffffffffu, myidx, (lane & 16) + k);
        uint4 rawv = *(const uint4*)&g_z[(size_t)r * 128 + c0];
        __half2 v[4];
        *(uint4*)v = rawv;
        mx[0] = __hmax2(mx[0], v[0]); mn[0] = __hmin2(mn[0], v[0]);
        mx[1] = __hmax2(mx[1], v[1]); mn[1] = __hmin2(mn[1], v[1]);
        mx[2] = __hmax2(mx[2], v[2]); mn[2] = __hmin2(mn[2], v[2]);
        mx[3] = __hmax2(mx[3], v[3]); mn[3] = __hmin2(mn[3], v[3]);
    }

    const float inv_m = 1.0f / (float)NK;
    float4 sum0 = *(const float4*)&g_stats2[c0];
    float4 sum1 = *(const float4*)&g_stats2[c0 + 4];
    float4 sq0 = *(const float4*)&g_stats2[128 + c0];
    float4 sq1 = *(const float4*)&g_stats2[128 + c0 + 4];
    float4 gm0 = *(const float4*)&gamma2[c0];
    float4 gm1 = *(const float4*)&gamma2[c0 + 4];
    float4 bt0 = *(const float4*)&beta2[c0];
    float4 bt1 = *(const float4*)&beta2[c0 + 4];
    float sm[8] = {sum0.x, sum0.y, sum0.z, sum0.w, sum1.x, sum1.y, sum1.z, sum1.w};
    float sq[8] = {sq0.x, sq0.y, sq0.z, sq0.w, sq1.x, sq1.y, sq1.z, sq1.w};
    float gm[8] = {gm0.x, gm0.y, gm0.z, gm0.w, gm1.x, gm1.y, gm1.z, gm1.w};
    float bt[8] = {bt0.x, bt0.y, bt0.z, bt0.w, bt1.x, bt1.y, bt1.z, bt1.w};

    float o[8];
#pragma unroll
    for (int j = 0; j < 8; j++) {
        float mean = sm[j] * inv_m;
        float var = sq[j] * inv_m - mean * mean;
        float sc = gm[j] * rsqrtf(var + EPSB);
        float bi = bt[j] - mean * sc;
        float2 fx = __half22float2(mx[j >> 1]);
        float2 fn = __half22float2(mn[j >> 1]);
        float vx = (j & 1) ? fx.y : fx.x;
        float vn = (j & 1) ? fn.y : fn.x;
        float m = (sc >= 0.f) ? vx : vn;
        o[j] = fmaxf(fmaf(sc, m, bi), 0.f);
    }
    size_t off = (size_t)p * 128 + c0;
    *(float4*)&out[off]     = make_float4(o[0], o[1], o[2], o[3]);
    *(float4*)&out[off + 4] = make_float4(o[4], o[5], o[6], o[7]);
}

// ---------------- launch --------------------------------------------------------
extern "C" void kernel_launch(void* const* d_in, const int* in_sizes, int n_in,
                              void* d_out, int out_size) {
    const float* feat = (const float*)d_in[0];
    const int* idx = (const int*)d_in[1];
    const float* W1 = (const float*)d_in[2];
    const float* b1 = (const float*)d_in[3];
    const float* g1 = (const float*)d_in[4];
    const float* be1 = (const float*)d_in[5];
    const float* W2 = (const float*)d_in[6];
    const float* b2 = (const float*)d_in[7];
    const float* g2 = (const float*)d_in[8];
    const float* be2 = (const float*)d_in[9];
    float* out = (float*)d_out;

    cudaFuncSetAttribute(gemm1_mma, cudaFuncAttributeMaxDynamicSharedMemorySize, G1_SMEM);
    cudaFuncSetAttribute(gemm2_mma, cudaFuncAttributeMaxDynamicSharedMemorySize, G2_SMEM);

    zero_kernel<<<(N_PTS + 255) / 256, 256>>>();
    count_kernel<<<(NK / 4 + 255) / 256, 256>>>((const int4*)idx);
    gemm1_mma<<<(N_PTS + 127) / 128, 256, G1_SMEM>>>(feat, W1, b1);
    gemm2_mma<<<(N_PTS + 63) / 64, 256, G2_SMEM>>>(W2, b2, g1, be1);
    gather_max_kernel<<<(N_PTS * 16 + 255) / 256, 256>>>(idx, g2, be2, out);
}